// round 1
// baseline (speedup 1.0000x reference)
#include <cuda_runtime.h>
#include <math.h>

#define NN 100000
#define NE 1600000
#define F  32

// Scratch (no allocations allowed): ~25.7 MB of __device__ globals.
__device__ float g_deg_out[NN];
__device__ float g_deg_in[NN];
__device__ float g_Sout[NN * F];   // segment_sum(w * x[dst]) into src
__device__ float g_Sin [NN * F];   // segment_sum(w * x[src]) into dst
__device__ float g_acc;            // final scalar accumulator

// ---------------------------------------------------------------- zero scratch
__global__ void k_zero() {
    int idx = blockIdx.x * blockDim.x + threadIdx.x;
    if (idx < NN * F) { g_Sout[idx] = 0.f; g_Sin[idx] = 0.f; }
    if (idx < NN)     { g_deg_out[idx] = 0.f; g_deg_in[idx] = 0.f; }
    if (idx == 0)     g_acc = 0.f;
}

// ------------------------------------------------- edge scatter (+ degrees)
// 8 threads per edge; each thread handles one float4 chunk of the 32 features.
__global__ void k_scatter(const float* __restrict__ x,
                          const float* __restrict__ ew,
                          const int*   __restrict__ ei) {
    int t = blockIdx.x * blockDim.x + threadIdx.x;
    if (t >= NE * 8) return;
    int e = t >> 3;
    int c = t & 7;
    int src = ei[e];
    int dst = ei[NE + e];
    float w = ew[e];

    const float4* x4 = reinterpret_cast<const float4*>(x);

    // S_out[src] += w * x[dst]
    float4 xd = x4[dst * 8 + c];
    float* so = &g_Sout[src * F + c * 4];
    atomicAdd(so + 0, w * xd.x);
    atomicAdd(so + 1, w * xd.y);
    atomicAdd(so + 2, w * xd.z);
    atomicAdd(so + 3, w * xd.w);

    // S_in[dst] += w * x[src]
    float4 xs = x4[src * 8 + c];
    float* si = &g_Sin[dst * F + c * 4];
    atomicAdd(si + 0, w * xs.x);
    atomicAdd(si + 1, w * xs.y);
    atomicAdd(si + 2, w * xs.z);
    atomicAdd(si + 3, w * xs.w);

    if (c == 0) {
        atomicAdd(&g_deg_out[src], w);
        atomicAdd(&g_deg_in[dst],  w);
    }
}

// ---------------------------------------------------------- per-node compute
// One warp per node, lane j = output feature j.
// z_pre = x@Az + P@Bz + Q@Cz + bz ; h_pre = x@Ah + P@Bh + Q@Ch + bh
// where Az = Wz[0,0]+Wz[1,0] (first 32 rows), Bz = Wz[0,1], Cz = Wz[1,1].
// H = (1 - sigmoid(z_pre)) * tanh(h_pre); acc += relu(H) . w_lin
__global__ void k_node(const float* __restrict__ x,
                       const float* __restrict__ Wz, const float* __restrict__ bz,
                       const float* __restrict__ Wh, const float* __restrict__ bh,
                       const float* __restrict__ wlin) {
    __shared__ float Az[32][32], Bz[32][32], Cz[32][32];
    __shared__ float Ah[32][32], Bh[32][32], Ch[32][32];
    __shared__ float partial[8];

    int tid = threadIdx.x;   // 256 threads = 8 warps
    // W layout [2,2,64,32]: flat = ((d*2+k)*64 + i)*32 + j  (i < 32 used; rest hits H=0)
    for (int idx = tid; idx < 1024; idx += 256) {
        int i = idx >> 5, j = idx & 31;
        Az[i][j] = Wz[i * 32 + j] + Wz[(128 + i) * 32 + j];
        Bz[i][j] = Wz[(64  + i) * 32 + j];
        Cz[i][j] = Wz[(192 + i) * 32 + j];
        Ah[i][j] = Wh[i * 32 + j] + Wh[(128 + i) * 32 + j];
        Bh[i][j] = Wh[(64  + i) * 32 + j];
        Ch[i][j] = Wh[(192 + i) * 32 + j];
    }
    __syncthreads();

    int warp = tid >> 5;
    int lane = tid & 31;
    int n = blockIdx.x * 8 + warp;

    float contrib = 0.f;
    if (n < NN) {
        float xj  = x[n * F + lane];
        float doi = 1.f / g_deg_out[n];
        float dii = 1.f / g_deg_in[n];
        float pj  = g_Sout[n * F + lane] * doi;
        float qj  = g_Sin [n * F + lane] * dii;

        float az = 0.f, ah = 0.f;
        #pragma unroll
        for (int i = 0; i < 32; i++) {
            float xi = __shfl_sync(0xffffffffu, xj, i);
            float pi = __shfl_sync(0xffffffffu, pj, i);
            float qi = __shfl_sync(0xffffffffu, qj, i);
            az += xi * Az[i][lane] + pi * Bz[i][lane] + qi * Cz[i][lane];
            ah += xi * Ah[i][lane] + pi * Bh[i][lane] + qi * Ch[i][lane];
        }
        az += bz[lane];
        ah += bh[lane];

        float z  = 1.f / (1.f + expf(-az));
        float ht = tanhf(ah);
        float Hj = (1.f - z) * ht;
        float r  = Hj > 0.f ? Hj : 0.f;
        contrib = r * wlin[lane];
    }

    // warp reduce
    #pragma unroll
    for (int o = 16; o; o >>= 1)
        contrib += __shfl_xor_sync(0xffffffffu, contrib, o);
    if (lane == 0) partial[warp] = contrib;
    __syncthreads();
    if (tid == 0) {
        float s = 0.f;
        #pragma unroll
        for (int w2 = 0; w2 < 8; w2++) s += partial[w2];
        atomicAdd(&g_acc, s);
    }
}

// ----------------------------------------------------------------- finalize
__global__ void k_final(float* __restrict__ out, const float* __restrict__ blin) {
    out[0] = g_acc / (float)NN + blin[0];
}

extern "C" void kernel_launch(void* const* d_in, const int* in_sizes, int n_in,
                              void* d_out, int out_size) {
    const float* x    = (const float*)d_in[0];
    const float* ew   = (const float*)d_in[1];
    const float* Wz   = (const float*)d_in[2];
    const float* bz   = (const float*)d_in[3];
    // d_in[4] = W_r, d_in[5] = b_r : dead (H=0 => H*R=0)
    const float* Wh   = (const float*)d_in[6];
    const float* bh   = (const float*)d_in[7];
    const float* wlin = (const float*)d_in[8];
    const float* blin = (const float*)d_in[9];
    const int*   ei   = (const int*)d_in[10];

    k_zero   <<<(NN * F + 255) / 256, 256>>>();
    k_scatter<<<(NE * 8 + 255) / 256, 256>>>(x, ew, ei);
    k_node   <<<(NN + 7) / 8, 256>>>(x, Wz, bz, Wh, bh, wlin);
    k_final  <<<1, 1>>>((float*)d_out, blin);
}

// round 2
// speedup vs baseline: 1.5687x; 1.5687x over previous
#include <cuda_runtime.h>
#include <math.h>

#define NN 100000
#define NE 1600000
#define F  32

// Scratch (no allocations allowed): ~25.7 MB of __device__ globals.
__device__ float g_deg_out[NN];
__device__ float g_deg_in[NN];
__device__ float g_Sout[NN * F];   // segment_sum(w * x[dst]) into src
__device__ float g_Sin [NN * F];   // segment_sum(w * x[src]) into dst
__device__ float g_acc;            // final scalar accumulator

__device__ __forceinline__ void red_v4(float* p, float a, float b, float c, float d) {
    asm volatile("red.global.add.v4.f32 [%0], {%1,%2,%3,%4};"
                 :: "l"(p), "f"(a), "f"(b), "f"(c), "f"(d) : "memory");
}

// ---------------------------------------------------------------- zero scratch
__global__ void k_zero() {
    int idx = blockIdx.x * blockDim.x + threadIdx.x;
    if (idx < NN * F) { g_Sout[idx] = 0.f; g_Sin[idx] = 0.f; }
    if (idx < NN)     { g_deg_out[idx] = 0.f; g_deg_in[idx] = 0.f; }
    if (idx == 0)     g_acc = 0.f;
}

// ------------------------------------------------- edge scatter (+ degrees)
// 8 threads per edge, one float4 feature-chunk each; vectorized red.global.
__global__ void k_scatter(const float* __restrict__ x,
                          const float* __restrict__ ew,
                          const int*   __restrict__ ei) {
    int t = blockIdx.x * blockDim.x + threadIdx.x;
    if (t >= NE * 8) return;
    int e = t >> 3;
    int c = t & 7;

    int src = __ldg(&ei[e]);
    int dst = __ldg(&ei[NE + e]);
    float w = __ldg(&ew[e]);

    const float4* x4 = reinterpret_cast<const float4*>(x);

    // S_out[src] += w * x[dst]
    float4 xd = __ldg(&x4[dst * 8 + c]);
    red_v4(&g_Sout[src * F + c * 4], w * xd.x, w * xd.y, w * xd.z, w * xd.w);

    // S_in[dst] += w * x[src]
    float4 xs = __ldg(&x4[src * 8 + c]);
    red_v4(&g_Sin[dst * F + c * 4], w * xs.x, w * xs.y, w * xs.z, w * xs.w);

    if (c == 0) {
        asm volatile("red.global.add.f32 [%0], %1;" :: "l"(&g_deg_out[src]), "f"(w) : "memory");
        asm volatile("red.global.add.f32 [%0], %1;" :: "l"(&g_deg_in[dst]),  "f"(w) : "memory");
    }
}

// ---------------------------------------------------------- per-node compute
// One warp per node, lane j = output feature j.
// z_pre = x@Az + P@Bz + Q@Cz + bz ; h_pre = x@Ah + P@Bh + Q@Ch + bh
// Az = Wz[0,0]+Wz[1,0] (first 32 rows; rest hits H=0), Bz = Wz[0,1], Cz = Wz[1,1].
// H = (1 - sigmoid(z_pre)) * tanh(h_pre); acc += relu(H) . w_lin
__global__ void k_node(const float* __restrict__ x,
                       const float* __restrict__ Wz, const float* __restrict__ bz,
                       const float* __restrict__ Wh, const float* __restrict__ bh,
                       const float* __restrict__ wlin) {
    __shared__ float Az[32][32], Bz[32][32], Cz[32][32];
    __shared__ float Ah[32][32], Bh[32][32], Ch[32][32];
    __shared__ float partial[8];

    int tid = threadIdx.x;   // 256 threads = 8 warps
    for (int idx = tid; idx < 1024; idx += 256) {
        int i = idx >> 5, j = idx & 31;
        Az[i][j] = Wz[i * 32 + j] + Wz[(128 + i) * 32 + j];
        Bz[i][j] = Wz[(64  + i) * 32 + j];
        Cz[i][j] = Wz[(192 + i) * 32 + j];
        Ah[i][j] = Wh[i * 32 + j] + Wh[(128 + i) * 32 + j];
        Bh[i][j] = Wh[(64  + i) * 32 + j];
        Ch[i][j] = Wh[(192 + i) * 32 + j];
    }
    __syncthreads();

    int warp = tid >> 5;
    int lane = tid & 31;
    int n = blockIdx.x * 8 + warp;

    float contrib = 0.f;
    if (n < NN) {
        float xj  = x[n * F + lane];
        float doi = 1.f / g_deg_out[n];
        float dii = 1.f / g_deg_in[n];
        float pj  = g_Sout[n * F + lane] * doi;
        float qj  = g_Sin [n * F + lane] * dii;

        float az = 0.f, ah = 0.f;
        #pragma unroll
        for (int i = 0; i < 32; i++) {
            float xi = __shfl_sync(0xffffffffu, xj, i);
            float pi = __shfl_sync(0xffffffffu, pj, i);
            float qi = __shfl_sync(0xffffffffu, qj, i);
            az += xi * Az[i][lane] + pi * Bz[i][lane] + qi * Cz[i][lane];
            ah += xi * Ah[i][lane] + pi * Bh[i][lane] + qi * Ch[i][lane];
        }
        az += bz[lane];
        ah += bh[lane];

        float z  = 1.f / (1.f + expf(-az));
        float ht = tanhf(ah);
        float Hj = (1.f - z) * ht;
        float r  = Hj > 0.f ? Hj : 0.f;
        contrib = r * wlin[lane];
    }

    #pragma unroll
    for (int o = 16; o; o >>= 1)
        contrib += __shfl_xor_sync(0xffffffffu, contrib, o);
    if (lane == 0) partial[warp] = contrib;
    __syncthreads();
    if (tid == 0) {
        float s = 0.f;
        #pragma unroll
        for (int w2 = 0; w2 < 8; w2++) s += partial[w2];
        atomicAdd(&g_acc, s);
    }
}

// ----------------------------------------------------------------- finalize
__global__ void k_final(float* __restrict__ out, const float* __restrict__ blin) {
    out[0] = g_acc / (float)NN + blin[0];
}

extern "C" void kernel_launch(void* const* d_in, const int* in_sizes, int n_in,
                              void* d_out, int out_size) {
    const float* x    = (const float*)d_in[0];
    const float* ew   = (const float*)d_in[1];
    const float* Wz   = (const float*)d_in[2];
    const float* bz   = (const float*)d_in[3];
    // d_in[4] = W_r, d_in[5] = b_r : dead (H=0 => H*R=0)
    const float* Wh   = (const float*)d_in[6];
    const float* bh   = (const float*)d_in[7];
    const float* wlin = (const float*)d_in[8];
    const float* blin = (const float*)d_in[9];
    const int*   ei   = (const int*)d_in[10];

    k_zero   <<<(NN * F + 255) / 256, 256>>>();
    k_scatter<<<(NE * 8 + 255) / 256, 256>>>(x, ew, ei);
    k_node   <<<(NN + 7) / 8, 256>>>(x, Wz, bz, Wh, bh, wlin);
    k_final  <<<1, 1>>>((float*)d_out, blin);
}

// round 3
// speedup vs baseline: 1.7657x; 1.1256x over previous
#include <cuda_runtime.h>
#include <cuda_fp16.h>
#include <math.h>

#define NN 100000
#define NE 1600000
#define F  32

// Scratch (no allocations allowed).
__device__ float   g_deg_out[NN];
__device__ float   g_deg_in[NN];
__device__ __half2 g_Sout[NN * F / 2];   // fp16 accumulators, 8 feats / 16B
__device__ __half2 g_Sin [NN * F / 2];
__device__ __half2 g_xh  [NN * F / 2];   // fp16 copy of x
__device__ float   g_acc;

__device__ __forceinline__ unsigned mulw_h2(unsigned u, float w) {
    __half2 h = *reinterpret_cast<__half2*>(&u);
    float2  f = __half22float2(h);
    __half2 r = __floats2half2_rn(f.x * w, f.y * w);
    return *reinterpret_cast<unsigned*>(&r);
}

__device__ __forceinline__ void red_v4h2(__half2* p, unsigned a, unsigned b,
                                         unsigned c, unsigned d) {
    asm volatile("red.global.add.noftz.v4.f16x2 [%0], {%1,%2,%3,%4};"
                 :: "l"(p), "r"(a), "r"(b), "r"(c), "r"(d) : "memory");
}

// ------------------------------------------- prep: zero scratch + x -> fp16
__global__ void k_prep(const float* __restrict__ x) {
    int idx = blockIdx.x * blockDim.x + threadIdx.x;   // over NN*F/2 = 1.6M
    if (idx < NN * F / 2) {
        g_Sout[idx] = __half2half2(__float2half(0.f));
        g_Sin [idx] = __half2half2(__float2half(0.f));
        float2 v = reinterpret_cast<const float2*>(x)[idx];
        g_xh[idx] = __floats2half2_rn(v.x, v.y);
    }
    if (idx < NN) { g_deg_out[idx] = 0.f; g_deg_in[idx] = 0.f; }
    if (idx == 0) g_acc = 0.f;
}

// ------------------------------------------------- edge scatter (+ degrees)
// 4 threads per edge; each thread handles 8 features (one 16B half2x4 chunk).
__global__ void k_scatter(const float* __restrict__ ew,
                          const int*   __restrict__ ei) {
    int t = blockIdx.x * blockDim.x + threadIdx.x;
    if (t >= NE * 4) return;
    int e = t >> 2;
    int c = t & 3;

    int src = __ldg(&ei[e]);
    int dst = __ldg(&ei[NE + e]);
    float w = __ldg(&ew[e]);

    const uint4* xh4 = reinterpret_cast<const uint4*>(g_xh);

    // S_out[src] += w * x[dst]
    uint4 xd = xh4[dst * 4 + c];
    red_v4h2(&g_Sout[src * (F / 2) + c * 4],
             mulw_h2(xd.x, w), mulw_h2(xd.y, w),
             mulw_h2(xd.z, w), mulw_h2(xd.w, w));

    // S_in[dst] += w * x[src]
    uint4 xs = xh4[src * 4 + c];
    red_v4h2(&g_Sin[dst * (F / 2) + c * 4],
             mulw_h2(xs.x, w), mulw_h2(xs.y, w),
             mulw_h2(xs.z, w), mulw_h2(xs.w, w));

    if (c == 0) {
        asm volatile("red.global.add.f32 [%0], %1;" :: "l"(&g_deg_out[src]), "f"(w) : "memory");
        asm volatile("red.global.add.f32 [%0], %1;" :: "l"(&g_deg_in[dst]),  "f"(w) : "memory");
    }
}

// ---------------------------------------------------------- per-node compute
// One warp per node, lane j = output feature j. R gate dead (H=0).
__global__ void k_node(const float* __restrict__ x,
                       const float* __restrict__ Wz, const float* __restrict__ bz,
                       const float* __restrict__ Wh, const float* __restrict__ bh,
                       const float* __restrict__ wlin) {
    __shared__ float Az[32][32], Bz[32][32], Cz[32][32];
    __shared__ float Ah[32][32], Bh[32][32], Ch[32][32];
    __shared__ float partial[8];

    int tid = threadIdx.x;   // 256 threads = 8 warps
    for (int idx = tid; idx < 1024; idx += 256) {
        int i = idx >> 5, j = idx & 31;
        Az[i][j] = Wz[i * 32 + j] + Wz[(128 + i) * 32 + j];
        Bz[i][j] = Wz[(64  + i) * 32 + j];
        Cz[i][j] = Wz[(192 + i) * 32 + j];
        Ah[i][j] = Wh[i * 32 + j] + Wh[(128 + i) * 32 + j];
        Bh[i][j] = Wh[(64  + i) * 32 + j];
        Ch[i][j] = Wh[(192 + i) * 32 + j];
    }
    __syncthreads();

    int warp = tid >> 5;
    int lane = tid & 31;
    int n = blockIdx.x * 8 + warp;

    float contrib = 0.f;
    if (n < NN) {
        const __half* Sout_h = reinterpret_cast<const __half*>(g_Sout);
        const __half* Sin_h  = reinterpret_cast<const __half*>(g_Sin);

        float xj  = x[n * F + lane];
        float doi = 1.f / g_deg_out[n];
        float dii = 1.f / g_deg_in[n];
        float pj  = __half2float(Sout_h[n * F + lane]) * doi;
        float qj  = __half2float(Sin_h [n * F + lane]) * dii;

        float az = 0.f, ah = 0.f;
        #pragma unroll
        for (int i = 0; i < 32; i++) {
            float xi = __shfl_sync(0xffffffffu, xj, i);
            float pi = __shfl_sync(0xffffffffu, pj, i);
            float qi = __shfl_sync(0xffffffffu, qj, i);
            az += xi * Az[i][lane] + pi * Bz[i][lane] + qi * Cz[i][lane];
            ah += xi * Ah[i][lane] + pi * Bh[i][lane] + qi * Ch[i][lane];
        }
        az += bz[lane];
        ah += bh[lane];

        float z  = 1.f / (1.f + expf(-az));
        float ht = tanhf(ah);
        float Hj = (1.f - z) * ht;
        float r  = Hj > 0.f ? Hj : 0.f;
        contrib = r * wlin[lane];
    }

    #pragma unroll
    for (int o = 16; o; o >>= 1)
        contrib += __shfl_xor_sync(0xffffffffu, contrib, o);
    if (lane == 0) partial[warp] = contrib;
    __syncthreads();
    if (tid == 0) {
        float s = 0.f;
        #pragma unroll
        for (int w2 = 0; w2 < 8; w2++) s += partial[w2];
        atomicAdd(&g_acc, s);
    }
}

// ----------------------------------------------------------------- finalize
__global__ void k_final(float* __restrict__ out, const float* __restrict__ blin) {
    out[0] = g_acc / (float)NN + blin[0];
}

extern "C" void kernel_launch(void* const* d_in, const int* in_sizes, int n_in,
                              void* d_out, int out_size) {
    const float* x    = (const float*)d_in[0];
    const float* ew   = (const float*)d_in[1];
    const float* Wz   = (const float*)d_in[2];
    const float* bz   = (const float*)d_in[3];
    // d_in[4] = W_r, d_in[5] = b_r : dead (H=0 => H*R=0)
    const float* Wh   = (const float*)d_in[6];
    const float* bh   = (const float*)d_in[7];
    const float* wlin = (const float*)d_in[8];
    const float* blin = (const float*)d_in[9];
    const int*   ei   = (const int*)d_in[10];

    k_prep   <<<(NN * F / 2 + 255) / 256, 256>>>(x);
    k_scatter<<<(NE * 4 + 255) / 256, 256>>>(ew, ei);
    k_node   <<<(NN + 7) / 8, 256>>>(x, Wz, bz, Wh, bh, wlin);
    k_final  <<<1, 1>>>((float*)d_out, blin);
}